// round 9
// baseline (speedup 1.0000x reference)
#include <cuda_runtime.h>
#include <math.h>

// Problem constants
#define VD    256          // embedding dim D
#define VD4   64           // D / 4
#define LL    32           // tokens per sequence
#define MM    4096         // mems rows
#define CC    4096         // cands rows
#define ROWS  (MM + 1)     // mems_enc rows (mems + xs)
#define EPS   1e-8f
#define NB    512          // persistent grid size (<= 148*4, all co-resident)
#define NPART 512          // partial rows (one per block), 8 rows each

// Scratch (allocation-free: __device__ globals)
__device__ float g_mems_enc[ROWS * VD];
__device__ float g_cos[ROWS];
__device__ float g_partial[NPART * VD];
__device__ float g_lhs[VD];
__device__ unsigned g_bar_count = 0;
__device__ unsigned g_bar_gen   = 0;

// ---------------------------------------------------------------------------
// Grid-wide barrier (threadfence-reduction pattern). Safe: grid fully resident.
// ---------------------------------------------------------------------------
__device__ __forceinline__ void grid_sync()
{
    __syncthreads();
    if (threadIdx.x == 0) {
        unsigned gen = *(volatile unsigned*)&g_bar_gen;
        __threadfence();                       // publish this block's phase writes
        if (atomicAdd(&g_bar_count, 1u) == (unsigned)(gridDim.x - 1)) {
            g_bar_count = 0;
            __threadfence();
            *(volatile unsigned*)&g_bar_gen = gen + 1;
        } else {
            while (*(volatile unsigned*)&g_bar_gen == gen) { __nanosleep(32); }
        }
        __threadfence();                       // acquire
    }
    __syncthreads();
}

// ---------------------------------------------------------------------------
// The whole network in one persistent kernel.
// 256 threads: 4 groups of 64; group g handles one sequence/row per task,
// thread j (0..63) owns one float4 column.
// ---------------------------------------------------------------------------
__global__ __launch_bounds__(256, 4)
void mega_kernel(const int* __restrict__ xs,
                 const int* __restrict__ mems,
                 const int* __restrict__ ys,
                 const int* __restrict__ cands,
                 const float* __restrict__ lt,
                 const float* __restrict__ freqs,
                 float* __restrict__ out_xs,
                 float* __restrict__ out_ys)
{
    __shared__ int    toks[4][LL];
    __shared__ float  ws[4][LL];
    __shared__ float  sred[8];
    __shared__ float4 scomb[4][VD4];
    __shared__ float  red[4][2][3];

    const int t    = threadIdx.x;
    const int g    = t >> 6;
    const int j    = t & 63;
    const int lane = t & 31;
    const int wid  = t >> 5;

    const float4* __restrict__ lt4  = reinterpret_cast<const float4*>(lt);
    float4* enc4  = reinterpret_cast<float4*>(g_mems_enc);
    const float4* enc4c = reinterpret_cast<const float4*>(g_mems_enc);

    // ======== Phase 1: encode mems + xs (4097 seqs, 1025 tasks) ========
    for (int task = blockIdx.x; task < 1025; task += NB) {
        const int s = task * 4 + g;
        const bool active = (s < MM + 1);
        const int* src = mems;
        float4* dst = nullptr;
        if (active) {
            if (s < MM) { src = mems + (size_t)s * LL; dst = enc4 + (size_t)s  * VD4; }
            else        { src = xs;                    dst = enc4 + (size_t)MM * VD4; }
        }
        if (active && j < LL) {
            int tok = src[j];
            toks[g][j] = tok;
            float w = freqs[tok];
            float sq = w * w;
            #pragma unroll
            for (int o = 16; o; o >>= 1) sq += __shfl_xor_sync(0xFFFFFFFFu, sq, o);
            ws[g][j] = w * rsqrtf(sq);
        }
        __syncthreads();
        if (active) {
            float4 acc = make_float4(0.f, 0.f, 0.f, 0.f);
            #pragma unroll
            for (int l = 0; l < LL; l++) {
                const float w = ws[g][l];
                const float4 e = lt4[(size_t)toks[g][l] * VD4 + j];
                acc.x = fmaf(w, e.x, acc.x);
                acc.y = fmaf(w, e.y, acc.y);
                acc.z = fmaf(w, e.z, acc.z);
                acc.w = fmaf(w, e.w, acc.w);
            }
            __stcs(dst + j, acc);          // streaming: keep lt L2-resident
        }
        __syncthreads();
    }
    grid_sync();

    // ======== Phase 2: cosine of each enc row vs row MM (1025 tasks) ========
    for (int task = blockIdx.x; task < 1025; task += NB) {
        const int r = task * 4 + g;
        if (r < ROWS) {
            const float4 mv = __ldcs(enc4c + (size_t)r  * VD4 + j);
            const float4 xv = enc4c[(size_t)MM * VD4 + j];
            float dot = mv.x * xv.x + mv.y * xv.y + mv.z * xv.z + mv.w * xv.w;
            float mn  = mv.x * mv.x + mv.y * mv.y + mv.z * mv.z + mv.w * mv.w;
            float xn  = xv.x * xv.x + xv.y * xv.y + xv.z * xv.z + xv.w * xv.w;
            #pragma unroll
            for (int o = 16; o; o >>= 1) {
                dot += __shfl_xor_sync(0xFFFFFFFFu, dot, o);
                mn  += __shfl_xor_sync(0xFFFFFFFFu, mn, o);
                xn  += __shfl_xor_sync(0xFFFFFFFFu, xn, o);
            }
            if (lane == 0) {
                const int wig = j >> 5;
                red[g][wig][0] = dot; red[g][wig][1] = mn; red[g][wig][2] = xn;
            }
        }
        __syncthreads();
        if (r < ROWS && j == 0) {
            float d  = red[g][0][0] + red[g][1][0];
            float m2 = red[g][0][1] + red[g][1][1];
            float x2 = red[g][0][2] + red[g][1][2];
            float an = fmaxf(sqrtf(x2), EPS);
            float bn = fmaxf(sqrtf(m2), EPS);
            g_cos[r] = d / (an * bn);
        }
        __syncthreads();
    }
    grid_sync();

    // ======== Phase 3: softmax stats (per-block, redundant) + partials ========
    {
        // max over g_cos
        float m = -INFINITY;
        for (int r = t; r < ROWS; r += 256) m = fmaxf(m, g_cos[r]);
        #pragma unroll
        for (int o = 16; o; o >>= 1) m = fmaxf(m, __shfl_xor_sync(0xFFFFFFFFu, m, o));
        if (lane == 0) sred[wid] = m;
        __syncthreads();
        {
            float mm = (t < 8) ? sred[t] : -INFINITY;
            if (wid == 0) {
                #pragma unroll
                for (int o = 4; o; o >>= 1) mm = fmaxf(mm, __shfl_xor_sync(0xFFFFFFFFu, mm, o));
                if (lane == 0) sred[0] = mm;
            }
        }
        __syncthreads();
        m = sred[0];
        __syncthreads();

        float s = 0.0f;
        for (int r = t; r < ROWS; r += 256) s += __expf(g_cos[r] - m);
        #pragma unroll
        for (int o = 16; o; o >>= 1) s += __shfl_xor_sync(0xFFFFFFFFu, s, o);
        if (lane == 0) sred[wid] = s;
        __syncthreads();
        {
            float ss = (t < 8) ? sred[t] : 0.0f;
            if (wid == 0) {
                #pragma unroll
                for (int o = 4; o; o >>= 1) ss += __shfl_xor_sync(0xFFFFFFFFu, ss, o);
                if (lane == 0) sred[0] = ss;
            }
        }
        __syncthreads();
        const float inv = 1.0f / sred[0];

        // partial weighted sum: 8 contiguous rows per block (2 per group)
        const int base = blockIdx.x * 8 + g * 2;
        float4 acc = make_float4(0.f, 0.f, 0.f, 0.f);
        #pragma unroll
        for (int k = 0; k < 2; k++) {
            const int r = base + k;                       // always < 4096
            const float a = __expf(g_cos[r] - m) * inv;
            const float4 e = __ldcs(enc4c + (size_t)r * VD4 + j);
            acc.x = fmaf(a, e.x, acc.x);
            acc.y = fmaf(a, e.y, acc.y);
            acc.z = fmaf(a, e.z, acc.z);
            acc.w = fmaf(a, e.w, acc.w);
        }
        if (blockIdx.x == 0 && g == 0) {                  // fold row 4096 (xs)
            const float a = __expf(g_cos[MM] - m) * inv;
            const float4 e = enc4c[(size_t)MM * VD4 + j];
            acc.x = fmaf(a, e.x, acc.x);
            acc.y = fmaf(a, e.y, acc.y);
            acc.z = fmaf(a, e.z, acc.z);
            acc.w = fmaf(a, e.w, acc.w);
        }
        scomb[g][j] = acc;
        __syncthreads();
        if (g == 0) {
            float4 a0 = scomb[0][j], a1 = scomb[1][j], a2 = scomb[2][j], a3 = scomb[3][j];
            float4 r;
            r.x = (a0.x + a1.x) + (a2.x + a3.x);
            r.y = (a0.y + a1.y) + (a2.y + a3.y);
            r.z = (a0.z + a1.z) + (a2.z + a3.z);
            r.w = (a0.w + a1.w) + (a2.w + a3.w);
            reinterpret_cast<float4*>(g_partial)[(size_t)blockIdx.x * VD4 + j] = r;
        }
    }
    grid_sync();

    // ======== Phase 4: reduce 512 partial rows -> g_lhs (blocks 0..63) ========
    if (blockIdx.x < VD4) {
        const int col = blockIdx.x;
        const float4* __restrict__ p4 = reinterpret_cast<const float4*>(g_partial);
        float4 v0 = p4[(size_t)t         * VD4 + col];
        float4 v1 = p4[(size_t)(t + 256) * VD4 + col];
        float4 v = make_float4(v0.x + v1.x, v0.y + v1.y, v0.z + v1.z, v0.w + v1.w);
        #pragma unroll
        for (int o = 16; o; o >>= 1) {
            v.x += __shfl_xor_sync(0xFFFFFFFFu, v.x, o);
            v.y += __shfl_xor_sync(0xFFFFFFFFu, v.y, o);
            v.z += __shfl_xor_sync(0xFFFFFFFFu, v.z, o);
            v.w += __shfl_xor_sync(0xFFFFFFFFu, v.w, o);
        }
        if (lane == 0) scomb[0][wid] = v;
        __syncthreads();
        if (t < 32) {
            float4 r = (lane < 8) ? scomb[0][lane] : make_float4(0.f, 0.f, 0.f, 0.f);
            #pragma unroll
            for (int o = 4; o; o >>= 1) {
                r.x += __shfl_xor_sync(0xFFFFFFFFu, r.x, o);
                r.y += __shfl_xor_sync(0xFFFFFFFFu, r.y, o);
                r.z += __shfl_xor_sync(0xFFFFFFFFu, r.z, o);
                r.w += __shfl_xor_sync(0xFFFFFFFFu, r.w, o);
            }
            if (lane == 0) reinterpret_cast<float4*>(g_lhs)[col] = r;
        }
    }
    grid_sync();

    // ======== Phase 5: tile lhs into out_xs + encode ys/cands (2050 tasks) ====
    const float4 lv = reinterpret_cast<const float4*>(g_lhs)[j];
    float4* outxs4 = reinterpret_cast<float4*>(out_xs);
    float4* outys4 = reinterpret_cast<float4*>(out_ys);

    for (int task = blockIdx.x; task < 2050; task += NB) {
        if (task < 1025) {
            const int row = task * 4 + g;
            if (row <= CC)
                __stcs(outxs4 + (size_t)row * VD4 + j, lv);
        } else {
            const int s2 = (task - 1025) * 4 + g;        // 0..4096: ys + cands
            const bool active = (s2 < 4097);
            const int* src = cands;
            float4* dst = nullptr;
            if (active) {
                if (s2 == 0) { src = ys; dst = outys4; }
                else {
                    const int c = s2 - 1;
                    src = cands + (size_t)c * LL;
                    dst = outys4 + (size_t)(1 + c) * VD4;
                }
            }
            if (active && j < LL) {
                int tok = src[j];
                toks[g][j] = tok;
                float w = freqs[tok];
                float sq = w * w;
                #pragma unroll
                for (int o = 16; o; o >>= 1) sq += __shfl_xor_sync(0xFFFFFFFFu, sq, o);
                ws[g][j] = w * rsqrtf(sq);
            }
            __syncthreads();
            if (active) {
                float4 acc = make_float4(0.f, 0.f, 0.f, 0.f);
                #pragma unroll
                for (int l = 0; l < LL; l++) {
                    const float w = ws[g][l];
                    const float4 e = lt4[(size_t)toks[g][l] * VD4 + j];
                    acc.x = fmaf(w, e.x, acc.x);
                    acc.y = fmaf(w, e.y, acc.y);
                    acc.z = fmaf(w, e.z, acc.z);
                    acc.w = fmaf(w, e.w, acc.w);
                }
                __stcs(dst + j, acc);
            }
            __syncthreads();
        }
    }
}

// ---------------------------------------------------------------------------
extern "C" void kernel_launch(void* const* d_in, const int* in_sizes, int n_in,
                              void* d_out, int out_size)
{
    const int*   xs    = (const int*)  d_in[0];
    const int*   mems  = (const int*)  d_in[1];
    const int*   ys    = (const int*)  d_in[2];
    const int*   cands = (const int*)  d_in[3];
    const float* lt    = (const float*)d_in[4];
    const float* freqs = (const float*)d_in[5];

    float* out    = (float*)d_out;
    float* out_xs = out;                          // [C+1, D]
    float* out_ys = out + (size_t)(CC + 1) * VD;  // [C+1, D]

    mega_kernel<<<NB, 256>>>(xs, mems, ys, cands, lt, freqs, out_xs, out_ys);
}

// round 11
// speedup vs baseline: 1.0936x; 1.0936x over previous
#include <cuda_runtime.h>
#include <math.h>

// Problem constants
#define VD    256          // embedding dim D
#define VD4   64           // D / 4
#define LL    32           // tokens per sequence
#define MM    4096         // mems rows
#define CC    4096         // cands rows
#define ROWS  (MM + 1)     // mems_enc rows (mems + xs)
#define NSEQ  (MM + 2 + CC)// all sequences: mems, xs, ys, cands
#define EPS   1e-8f
#define NLHS  256          // blocks for att @ mems_enc partial stage

// Scratch (allocation-free: __device__ globals)
__device__ float g_mems_enc[ROWS * VD];
__device__ float g_cos[ROWS];
__device__ float g_partial[NLHS * VD];
__device__ float g_lhs[VD];
__device__ unsigned g_done = 0;     // last-block-done counter (reset by last block)

// ---------------------------------------------------------------------------
// Kernel 1: encode ALL sequences (mems, xs, ys, cands) — one launch.
// ceil(NSEQ/4) blocks x 256 threads; each 64-thread group = 1 sequence,
// thread j (0..63) owns one float4 column.
// enc rows -> PLAIN stores (re-read by cos/partial: keep in L2; only 4MB).
// ys/cands out -> streaming stores (never re-read).
// ---------------------------------------------------------------------------
__global__ void encode_kernel(const int* __restrict__ xs,
                              const int* __restrict__ mems,
                              const int* __restrict__ ys,
                              const int* __restrict__ cands,
                              const float* __restrict__ lt,
                              const float* __restrict__ freqs,
                              float* __restrict__ out_ys)
{
    __shared__ int   toks[4][LL];
    __shared__ float ws[4][LL];

    const int t = threadIdx.x;
    const int g = t >> 6;
    const int j = t & 63;
    const int s = blockIdx.x * 4 + g;

    const bool active = (s < NSEQ);

    const int* src = mems;
    float4* dst = nullptr;
    bool to_enc = false;
    if (active) {
        if (s < MM) {
            src = mems + (size_t)s * LL;
            dst = reinterpret_cast<float4*>(g_mems_enc) + (size_t)s * VD4;
            to_enc = true;
        } else if (s == MM) {
            src = xs;
            dst = reinterpret_cast<float4*>(g_mems_enc) + (size_t)MM * VD4;
            to_enc = true;
        } else if (s == MM + 1) {
            src = ys;
            dst = reinterpret_cast<float4*>(out_ys);
        } else {
            const int c = s - (MM + 2);
            src = cands + (size_t)c * LL;
            dst = reinterpret_cast<float4*>(out_ys) + (size_t)(1 + c) * VD4;
        }
    }

    if (active && j < LL) {
        int tok = src[j];
        toks[g][j] = tok;
        float w = freqs[tok];
        float sq = w * w;
        #pragma unroll
        for (int o = 16; o; o >>= 1) sq += __shfl_xor_sync(0xFFFFFFFFu, sq, o);
        ws[g][j] = w * rsqrtf(sq);
    }
    __syncthreads();

    if (active) {
        const float4* __restrict__ lt4 = reinterpret_cast<const float4*>(lt);
        float4 acc = make_float4(0.f, 0.f, 0.f, 0.f);
        #pragma unroll
        for (int l = 0; l < LL; l++) {
            const float w = ws[g][l];
            const float4 e = lt4[(size_t)toks[g][l] * VD4 + j];
            acc.x = fmaf(w, e.x, acc.x);
            acc.y = fmaf(w, e.y, acc.y);
            acc.z = fmaf(w, e.z, acc.z);
            acc.w = fmaf(w, e.w, acc.w);
        }
        if (to_enc) dst[j] = acc;            // plain: keep enc in L2 for tail
        else        __stcs(dst + j, acc);    // streaming: never re-read
    }
}

// ---------------------------------------------------------------------------
// Kernel 2: cosine of every mems_enc row vs row M (xs). 4 rows per block,
// 64 threads per row, float4. Plain loads (L2-hot after encode).
// ---------------------------------------------------------------------------
__global__ void cos_kernel()
{
    __shared__ float red[4][2][3];

    const int t = threadIdx.x;
    const int g = t >> 6;
    const int j = t & 63;
    const int r = blockIdx.x * 4 + g;
    if (r >= ROWS) return;

    const float4* __restrict__ enc4 = reinterpret_cast<const float4*>(g_mems_enc);
    const float4 mv = enc4[(size_t)r  * VD4 + j];
    const float4 xv = enc4[(size_t)MM * VD4 + j];

    float dot = mv.x * xv.x + mv.y * xv.y + mv.z * xv.z + mv.w * xv.w;
    float mn  = mv.x * mv.x + mv.y * mv.y + mv.z * mv.z + mv.w * mv.w;
    float xn  = xv.x * xv.x + xv.y * xv.y + xv.z * xv.z + xv.w * xv.w;

    #pragma unroll
    for (int o = 16; o; o >>= 1) {
        dot += __shfl_xor_sync(0xFFFFFFFFu, dot, o);
        mn  += __shfl_xor_sync(0xFFFFFFFFu, mn, o);
        xn  += __shfl_xor_sync(0xFFFFFFFFu, xn, o);
    }
    const int wig = j >> 5;
    if ((j & 31) == 0) {
        red[g][wig][0] = dot; red[g][wig][1] = mn; red[g][wig][2] = xn;
    }
    __syncthreads();

    if (j == 0) {
        float d  = red[g][0][0] + red[g][1][0];
        float m2 = red[g][0][1] + red[g][1][1];
        float x2 = red[g][0][2] + red[g][1][2];
        float an = fmaxf(sqrtf(x2), EPS);
        float bn = fmaxf(sqrtf(m2), EPS);
        g_cos[r] = d / (an * bn);
    }
}

// ---------------------------------------------------------------------------
// Kernel 3: fused softmax + partial att @ mems_enc + LAST-BLOCK final reduce.
// 256 blocks x 256 threads. Each block recomputes softmax stats from g_cos
// (16KB, L2-hot), computes its 16-row partial, writes it; the last block to
// finish reduces all 256 partial rows (L2-hot) into g_lhs and resets g_done.
// ---------------------------------------------------------------------------
__global__ void lhs_kernel()
{
    __shared__ float  sred[8];
    __shared__ float4 scomb[4][VD4];
    __shared__ bool   s_last;

    const int t = threadIdx.x;
    const int lane = t & 31;
    const int wid  = t >> 5;

    // --- softmax stats over g_cos ---
    float m = -INFINITY;
    for (int r = t; r < ROWS; r += 256) m = fmaxf(m, g_cos[r]);
    #pragma unroll
    for (int o = 16; o; o >>= 1) m = fmaxf(m, __shfl_xor_sync(0xFFFFFFFFu, m, o));
    if (lane == 0) sred[wid] = m;
    __syncthreads();
    {
        float mm = (t < 8) ? sred[t] : -INFINITY;
        if (wid == 0) {
            #pragma unroll
            for (int o = 4; o; o >>= 1) mm = fmaxf(mm, __shfl_xor_sync(0xFFFFFFFFu, mm, o));
            if (lane == 0) sred[0] = mm;
        }
    }
    __syncthreads();
    m = sred[0];
    __syncthreads();

    float s = 0.0f;
    for (int r = t; r < ROWS; r += 256) s += __expf(g_cos[r] - m);
    #pragma unroll
    for (int o = 16; o; o >>= 1) s += __shfl_xor_sync(0xFFFFFFFFu, s, o);
    if (lane == 0) sred[wid] = s;
    __syncthreads();
    {
        float ss = (t < 8) ? sred[t] : 0.0f;
        if (wid == 0) {
            #pragma unroll
            for (int o = 4; o; o >>= 1) ss += __shfl_xor_sync(0xFFFFFFFFu, ss, o);
            if (lane == 0) sred[0] = ss;
        }
    }
    __syncthreads();
    const float inv = 1.0f / sred[0];

    // --- partial weighted sum: 16 contiguous rows per block (4 per group) ---
    const int g = t >> 6;
    const int j = t & 63;
    const int base = (blockIdx.x * 4 + g) * 4;

    const float4* __restrict__ enc4 = reinterpret_cast<const float4*>(g_mems_enc);
    float4 acc = make_float4(0.f, 0.f, 0.f, 0.f);

    #pragma unroll
    for (int k = 0; k < 4; k++) {
        const int r = base + k;
        const float a = __expf(g_cos[r] - m) * inv;
        const float4 e = enc4[(size_t)r * VD4 + j];
        acc.x = fmaf(a, e.x, acc.x);
        acc.y = fmaf(a, e.y, acc.y);
        acc.z = fmaf(a, e.z, acc.z);
        acc.w = fmaf(a, e.w, acc.w);
    }
    if (blockIdx.x == 0 && g == 0) {          // fold row 4096 (xs)
        const float a = __expf(g_cos[MM] - m) * inv;
        const float4 e = enc4[(size_t)MM * VD4 + j];
        acc.x = fmaf(a, e.x, acc.x);
        acc.y = fmaf(a, e.y, acc.y);
        acc.z = fmaf(a, e.z, acc.z);
        acc.w = fmaf(a, e.w, acc.w);
    }

    scomb[g][j] = acc;
    __syncthreads();

    if (g == 0) {
        float4 a0 = scomb[0][j], a1 = scomb[1][j], a2 = scomb[2][j], a3 = scomb[3][j];
        float4 r;
        r.x = (a0.x + a1.x) + (a2.x + a3.x);
        r.y = (a0.y + a1.y) + (a2.y + a3.y);
        r.z = (a0.z + a1.z) + (a2.z + a3.z);
        r.w = (a0.w + a1.w) + (a2.w + a3.w);
        reinterpret_cast<float4*>(g_partial)[(size_t)blockIdx.x * VD4 + j] = r;
    }
    __syncthreads();

    // --- last-block-done: final reduce of 256 partial rows ---
    if (t == 0) {
        __threadfence();
        unsigned old = atomicAdd(&g_done, 1u);
        s_last = (old == NLHS - 1);
    }
    __syncthreads();
    if (!s_last) return;
    if (t == 0) { g_done = 0; __threadfence(); }   // reset for next graph replay

    // thread (g, j): sum partial rows g*64..g*64+63 for float4 column j
    const float4* __restrict__ p4 = reinterpret_cast<const float4*>(g_partial);
    float4 fin = make_float4(0.f, 0.f, 0.f, 0.f);
    #pragma unroll 8
    for (int b = g * 64; b < (g + 1) * 64; b++) {
        const float4 v = p4[(size_t)b * VD4 + j];
        fin.x += v.x; fin.y += v.y; fin.z += v.z; fin.w += v.w;
    }
    scomb[g][j] = fin;
    __syncthreads();

    if (g == 0) {
        float4 a0 = scomb[0][j], a1 = scomb[1][j], a2 = scomb[2][j], a3 = scomb[3][j];
        float4 r;
        r.x = (a0.x + a1.x) + (a2.x + a3.x);
        r.y = (a0.y + a1.y) + (a2.y + a3.y);
        r.z = (a0.z + a1.z) + (a2.z + a3.z);
        r.w = (a0.w + a1.w) + (a2.w + a3.w);
        reinterpret_cast<float4*>(g_lhs)[j] = r;
    }
}

// ---------------------------------------------------------------------------
// Kernel 4: tile g_lhs into xs_out (C+1 identical rows). float4, 4 rows/block,
// streaming stores.
// ---------------------------------------------------------------------------
__global__ void tile_kernel(float* __restrict__ out_xs)
{
    const int t = threadIdx.x;
    const int row = blockIdx.x * 4 + (t >> 6);
    const int j = t & 63;
    if (row <= CC) {
        const float4 v = reinterpret_cast<const float4*>(g_lhs)[j];
        __stcs(reinterpret_cast<float4*>(out_xs) + (size_t)row * VD4 + j, v);
    }
}

// ---------------------------------------------------------------------------
extern "C" void kernel_launch(void* const* d_in, const int* in_sizes, int n_in,
                              void* d_out, int out_size)
{
    const int*   xs    = (const int*)  d_in[0];
    const int*   mems  = (const int*)  d_in[1];
    const int*   ys    = (const int*)  d_in[2];
    const int*   cands = (const int*)  d_in[3];
    const float* lt    = (const float*)d_in[4];
    const float* freqs = (const float*)d_in[5];

    float* out    = (float*)d_out;
    float* out_xs = out;                          // [C+1, D]
    float* out_ys = out + (size_t)(CC + 1) * VD;  // [C+1, D]

    encode_kernel<<<(NSEQ + 3) / 4, VD>>>(xs, mems, ys, cands, lt, freqs, out_ys);
    cos_kernel<<<(ROWS + 3) / 4, VD>>>();
    lhs_kernel<<<NLHS, VD>>>();
    tile_kernel<<<(CC + 1 + 3) / 4, VD>>>(out_xs);
}